// round 15
// baseline (speedup 1.0000x reference)
#include <cuda_runtime.h>
#include <cuda_fp16.h>
#include <math.h>
#include <stdint.h>

// Problem dims
#define Q    64
#define SQ   32
#define CC   256
#define SC   256
#define H    768
#define D    128
#define QT   31
#define CT   255
#define QROWS (Q*QT)     // 1984
#define CROWS (CC*CT)    // 65280
#define NROWS (QROWS+CROWS)

#define PROJ_BLKS 526    // ceil(NROWS/128): upper bound on GEMM blocks
#define AUX_BLKS  577    // 320 pooled + 256 compact + 1 prep

// Scratch
__device__ __half g_colh[(size_t)NROWS * D];
__device__ float  g_denom[Q];
__device__ int    g_idx[CC * 256];
__device__ int    g_cnt[CC];
__device__ int    g_qoff[Q + 1];
__device__ int    g_gqidx[QROWS];
__device__ int    g_tile_qs[16], g_tile_qe[16], g_tile_rs[16];
__device__ int    g_ntiles;
__device__ int    g_nun;            // ticket counter; reset by maxsim at sequence end
__device__ int    g_unrows[NROWS];

// ---------------------------------------------------------------------------
// helpers
// ---------------------------------------------------------------------------
__device__ __forceinline__ void mma_tf32(float* c, const uint32_t* a, const uint32_t* b) {
    asm volatile(
        "mma.sync.aligned.m16n8k8.row.col.f32.tf32.tf32.f32 "
        "{%0,%1,%2,%3},{%4,%5,%6,%7},{%8,%9},{%0,%1,%2,%3};\n"
        : "+f"(c[0]), "+f"(c[1]), "+f"(c[2]), "+f"(c[3])
        : "r"(a[0]), "r"(a[1]), "r"(a[2]), "r"(a[3]), "r"(b[0]), "r"(b[1]));
}
__device__ __forceinline__ void mma_f16(float* c, const uint32_t* a, const uint32_t* b) {
    asm volatile(
        "mma.sync.aligned.m16n8k16.row.col.f32.f16.f16.f32 "
        "{%0,%1,%2,%3},{%4,%5,%6,%7},{%8,%9},{%0,%1,%2,%3};\n"
        : "+f"(c[0]), "+f"(c[1]), "+f"(c[2]), "+f"(c[3])
        : "r"(a[0]), "r"(a[1]), "r"(a[2]), "r"(a[3]), "r"(b[0]), "r"(b[1]));
}
__device__ __forceinline__ uint32_t smem_u32(const void* p) {
    uint32_t a;
    asm("{ .reg .u64 t; cvta.to.shared.u64 t, %1; cvt.u32.u64 %0, t; }" : "=r"(a) : "l"(p));
    return a;
}
#define CP_ASYNC16(dst_u32, src_ptr) \
    asm volatile("cp.async.ca.shared.global [%0], [%1], 16;" :: "r"(dst_u32), "l"(src_ptr))
#define CP_COMMIT() asm volatile("cp.async.commit_group;" ::: "memory")
#define CP_WAIT1()  asm volatile("cp.async.wait_group 1;" ::: "memory")
#define CP_WAIT0()  asm volatile("cp.async.wait_group 0;" ::: "memory")

// ---------------------------------------------------------------------------
// Kernel 1: unlist only — the single producer proj depends on.
// Grid 263 x 256.
// ---------------------------------------------------------------------------
__global__ void unlist_kernel(const int* __restrict__ qm,
                              const int* __restrict__ cm) {
    int t = threadIdx.x, lane = t & 31;
    int r = blockIdx.x * 256 + t;
    int m = 0;
    if (r < NROWS) {
        if (r < QROWS) { int q = r / QT, i = r % QT; m = qm[q * SQ + i + 1]; }
        else { int rc = r - QROWS; int c = rc / CT, j = rc % CT; m = cm[c * SC + j + 1]; }
    }
    unsigned bal = __ballot_sync(0xffffffffu, m != 0);
    int cnt = __popc(bal);
    int pre = __popc(bal & ((1u << lane) - 1));
    int base = 0;
    if (lane == 0 && cnt) base = atomicAdd(&g_nun, cnt);
    base = __shfl_sync(0xffffffffu, base, 0);
    if (m) g_unrows[base + pre] = r;
}

// ---------------------------------------------------------------------------
// Kernel 2: MEGAPROJ — blocks [0,526): projection GEMM over unmasked rows;
// blocks [526,1103): aux roles (pooled / doc compaction / q-prep), absorbed
// into proj's wave so their latency hides behind tensor work.
// ---------------------------------------------------------------------------
#define P_SA 36
#define P_SW 132
#define P_AS_F (128 * P_SA)
#define P_WS_F (32 * P_SW)
#define P_SMEM_FLOATS (2*P_AS_F + 2*P_WS_F + 256 + 128 + 256 + 128 + 128)
#define P_SMEM_BYTES (P_SMEM_FLOATS * 4)

__global__ __launch_bounds__(256) void proj_kernel(const float* __restrict__ qh,
                                                   const float* __restrict__ ch,
                                                   const float* __restrict__ Wm,
                                                   const float* __restrict__ bias,
                                                   const int*   __restrict__ qm,
                                                   const int*   __restrict__ cm,
                                                   float* __restrict__ out) {
    int t = threadIdx.x;
    int lane = t & 31, w = t >> 5;

    if (blockIdx.x >= PROJ_BLKS) {
        int b2 = blockIdx.x - PROJ_BLKS;
        if (b2 < 320) {
            // ---- pooled (fp32 exact) ----
            __shared__ float red[8];
            const float* src;
            float mask;
            float* dst;
            if (b2 < Q) {
                src  = qh + (size_t)b2 * SQ * H;
                mask = (float)qm[b2 * SQ];
                dst  = out + Q * CC + (size_t)b2 * H;
            } else {
                int c = b2 - Q;
                src  = ch + (size_t)c * SC * H;
                mask = (float)cm[c * SC];
                dst  = out + Q * CC + Q * H + (size_t)c * H;
            }
            float v[3];
            float s = 0.f;
#pragma unroll
            for (int it = 0; it < 3; it++) {
                float x = src[t + it * 256] * mask;
                v[it] = x;
                s += x * x;
            }
#pragma unroll
            for (int o = 16; o; o >>= 1) s += __shfl_xor_sync(0xffffffffu, s, o);
            if (lane == 0) red[w] = s;
            __syncthreads();
            if (t < 8) {
                float ss = red[t];
#pragma unroll
                for (int o = 4; o; o >>= 1) ss += __shfl_xor_sync(0xffu, ss, o);
                if (t == 0) red[0] = ss;
            }
            __syncthreads();
            float inv = 1.f / fmaxf(sqrtf(red[0]), 1e-12f);
#pragma unroll
            for (int it = 0; it < 3; it++) dst[t + it * 256] = v[it] * inv;

        } else if (b2 < 576) {
            // ---- doc compaction + cvec rep-row write ----
            __shared__ int wcnt[8];
            __shared__ int firstmask;
            __shared__ float s_cr[4];
            int c = b2 - 320;
            if (t == 0) firstmask = 1 << 30;
            __syncthreads();
            int valid = (t >= 1);
            int m = valid ? cm[c * SC + t] : 0;
            unsigned bal = __ballot_sync(0xffffffffu, m != 0);
            int pre = __popc(bal & ((1u << lane) - 1));
            if (lane == 0) wcnt[w] = __popc(bal);
            if (valid && !m) atomicMin(&firstmask, t);
            __syncthreads();
            int off = 0;
            for (int i = 0; i < w; i++) off += wcnt[i];
            if (valid && m) g_idx[c * 256 + off + pre] = t - 1;
            if (t == 0) {
                int total = 0;
                for (int i = 0; i < 8; i++) total += wcnt[i];
                if (firstmask < 256) { g_idx[c * 256 + total] = firstmask - 1; total++; }
                g_cnt[c] = total;
            }
            float v = (t < D) ? bias[t] : 0.f;
            float sq = v * v;
#pragma unroll
            for (int o = 16; o; o >>= 1) sq += __shfl_xor_sync(0xffffffffu, sq, o);
            if (lane == 0 && t < D) s_cr[w] = sq;
            __syncthreads();
            if (firstmask < 256 && t < D) {
                float tot = s_cr[0] + s_cr[1] + s_cr[2] + s_cr[3];
                float inv = 1.f / fmaxf(sqrtf(tot), 1e-12f);
                size_t row = (size_t)QROWS + (size_t)c * CT + (firstmask - 1);
                g_colh[row * D + t] = __float2half_rn(v * inv);
            }

        } else {
            // ---- q-side prep ----
            __shared__ int s_nu[64];
            __shared__ int s_qoff[65];
            if (t < 64) {
                int nu = 0;
                for (int i = 1; i < SQ; i++) nu += (qm[t * SQ + i] != 0);
                s_nu[t] = nu;
                g_denom[t] = (float)nu;
            }
            __syncthreads();
            if (t == 0) {
                int acc = 0;
                for (int q = 0; q < 64; q++) { s_qoff[q] = acc; acc += s_nu[q]; }
                s_qoff[64] = acc;
                int ntiles = 0, cur = 0;
                while (cur < 64) {
                    int qs = cur;
                    while (cur < 64 && (s_qoff[cur + 1] - s_qoff[qs]) <= 128) cur++;
                    g_tile_qs[ntiles] = qs;
                    g_tile_qe[ntiles] = cur;
                    g_tile_rs[ntiles] = s_qoff[qs];
                    ntiles++;
                }
                g_ntiles = ntiles;
            }
            __syncthreads();
            if (t < 65) g_qoff[t] = s_qoff[t];
            if (t < 64) {
                int pos = s_qoff[t];
                for (int i = 1; i < SQ; i++)
                    if (qm[t * SQ + i] != 0) g_gqidx[pos++] = t * QT + i - 1;
            }
        }
        return;
    }

    // ---- GEMM role ----
    int nun = g_nun;
    if (blockIdx.x * 128 >= nun) return;

    extern __shared__ float psm[];
    float* As0 = psm;
    float* As1 = psm + P_AS_F;
    float* Ws0 = psm + 2 * P_AS_F;
    float* Ws1 = Ws0 + P_WS_F;
    const float** srcp = (const float**)(psm + 2 * P_AS_F + 2 * P_WS_F);
    int*   rowid  = (int*)(srcp + 128);
    float* rowsq  = (float*)(rowid + 128);
    float* invn   = rowsq + 256;
    float* s_bias = invn + 128;

    int g = lane >> 2, tg = lane & 3;
    int mw = w & 3, nw = w >> 2;
    int m_warp = mw * 32, n_warp = nw * 64;

    if (t < 128) {
        s_bias[t] = bias[t];
        int idx = blockIdx.x * 128 + t;
        if (idx < nun) {
            int r = g_unrows[idx];
            rowid[t] = r;
            if (r < QROWS) {
                int q = r / QT, i = r % QT;
                srcp[t] = qh + (size_t)(q * SQ + i + 1) * H;
            } else {
                int rc = r - QROWS;
                int c = rc / CT, j = rc % CT;
                srcp[t] = ch + (size_t)(c * SC + j + 1) * H;
            }
        } else {
            rowid[t] = -1;
            srcp[t] = qh;
        }
    }
    __syncthreads();

#define PSTAGE(bufA, bufW, KT) do {                                             \
    _Pragma("unroll")                                                           \
    for (int itc = 0; itc < 4; itc++) {                                         \
        int idx = t + itc * 256;                                                \
        int m = idx >> 3, k4 = idx & 7;                                         \
        CP_ASYNC16(smem_u32((bufA) + m * P_SA + k4 * 4), srcp[m] + (KT) + k4 * 4); \
    }                                                                           \
    _Pragma("unroll")                                                           \
    for (int itc = 0; itc < 4; itc++) {                                         \
        int idx = t + itc * 256;                                                \
        int k = idx >> 5, d4 = idx & 31;                                        \
        CP_ASYNC16(smem_u32((bufW) + k * P_SW + d4 * 4),                        \
                   Wm + (size_t)((KT) + k) * D + d4 * 4);                       \
    }                                                                           \
} while (0)

    PSTAGE(As0, Ws0, 0);
    CP_COMMIT();

    float acc[2][8][4];
#pragma unroll
    for (int mt = 0; mt < 2; mt++)
#pragma unroll
        for (int nt4 = 0; nt4 < 8; nt4++)
#pragma unroll
            for (int i = 0; i < 4; i++) acc[mt][nt4][i] = 0.f;

    for (int it = 0; it < 24; it++) {
        if (it < 23) {
            if (it & 1) PSTAGE(As0, Ws0, (it + 1) * 32);
            else        PSTAGE(As1, Ws1, (it + 1) * 32);
            CP_COMMIT();
            CP_WAIT1();
        } else {
            CP_WAIT0();
        }
        __syncthreads();
        const float* A = (it & 1) ? As1 : As0;
        const float* W = (it & 1) ? Ws1 : Ws0;
#pragma unroll
        for (int ks = 0; ks < 4; ks++) {
            int k0 = ks * 8;
            uint32_t afr[2][4], bfr[8][2];
#pragma unroll
            for (int mt = 0; mt < 2; mt++) {
                int base = m_warp + mt * 16;
                afr[mt][0] = __float_as_uint(A[(base + g)     * P_SA + k0 + tg]);
                afr[mt][1] = __float_as_uint(A[(base + g + 8) * P_SA + k0 + tg]);
                afr[mt][2] = __float_as_uint(A[(base + g)     * P_SA + k0 + tg + 4]);
                afr[mt][3] = __float_as_uint(A[(base + g + 8) * P_SA + k0 + tg + 4]);
            }
#pragma unroll
            for (int nt4 = 0; nt4 < 8; nt4++) {
                int col = n_warp + nt4 * 8 + g;
                bfr[nt4][0] = __float_as_uint(W[(k0 + tg)     * P_SW + col]);
                bfr[nt4][1] = __float_as_uint(W[(k0 + tg + 4) * P_SW + col]);
            }
#pragma unroll
            for (int mt = 0; mt < 2; mt++)
#pragma unroll
                for (int nt4 = 0; nt4 < 8; nt4++)
                    mma_tf32(acc[mt][nt4], afr[mt], bfr[nt4]);
        }
        __syncthreads();
    }

#pragma unroll
    for (int mt = 0; mt < 2; mt++)
#pragma unroll
        for (int nt4 = 0; nt4 < 8; nt4++)
#pragma unroll
            for (int i = 0; i < 4; i++)
                acc[mt][nt4][i] += s_bias[n_warp + nt4 * 8 + 2 * tg + (i & 1)];

    float pr[2][2];
#pragma unroll
    for (int mt = 0; mt < 2; mt++)
#pragma unroll
        for (int h = 0; h < 2; h++) {
            float s = 0.f;
#pragma unroll
            for (int nt4 = 0; nt4 < 8; nt4++) {
                float c0 = acc[mt][nt4][2 * h], c1 = acc[mt][nt4][2 * h + 1];
                s += c0 * c0 + c1 * c1;
            }
            pr[mt][h] = s;
        }
#pragma unroll
    for (int off = 1; off <= 2; off <<= 1) {
#pragma unroll
        for (int mt = 0; mt < 2; mt++)
#pragma unroll
            for (int h = 0; h < 2; h++)
                pr[mt][h] += __shfl_xor_sync(0xffffffffu, pr[mt][h], off);
    }
    if (tg == 0) {
#pragma unroll
        for (int mt = 0; mt < 2; mt++)
#pragma unroll
            for (int h = 0; h < 2; h++)
                rowsq[(m_warp + mt * 16 + g + 8 * h) * 2 + nw] = pr[mt][h];
    }
    __syncthreads();
    if (t < 128) {
        float s = rowsq[t * 2] + rowsq[t * 2 + 1];
        invn[t] = 1.f / fmaxf(sqrtf(s), 1e-12f);
    }
    __syncthreads();

#pragma unroll
    for (int mt = 0; mt < 2; mt++)
#pragma unroll
        for (int h = 0; h < 2; h++) {
            int r = m_warp + mt * 16 + g + 8 * h;
            int grow = rowid[r];
            if (grow >= 0) {
                float inv = invn[r];
                __half* dst = g_colh + (size_t)grow * D;
#pragma unroll
                for (int nt4 = 0; nt4 < 8; nt4++) {
                    int col = n_warp + nt4 * 8 + 2 * tg;
                    *(__half2*)(dst + col) =
                        __floats2half2_rn(acc[mt][nt4][2 * h] * inv,
                                          acc[mt][nt4][2 * h + 1] * inv);
                }
            }
        }
#undef PSTAGE
}

// ---------------------------------------------------------------------------
// Kernel 3: fused maxsim — unchanged from round 14 (proven at 2 CTA/SM).
// ---------------------------------------------------------------------------
#define MS_SAH 136
#define MS_SBH 136
#define MSA_HALFS (128 * MS_SAH)
#define MSB_HALFS (256 * MS_SBH)
#define MS_SMEM_BYTES ((MSA_HALFS + MSB_HALFS) * 2 + (4 * 128) * 4 + 256 * 4 + 128 * 4 + 12 * 4)

#define MS_STAGEA(TT_) do {                                                      \
    int rs_ = g_tile_rs[TT_];                                                    \
    int rows_ = g_qoff[g_tile_qe[TT_]] - rs_;                                    \
    int chunks_ = rows_ * 16;                                                    \
    _Pragma("unroll")                                                            \
    for (int j = 0; j < 8; j++) {                                                \
        int idx = t + j * 256;                                                   \
        if (idx < chunks_) {                                                     \
            int m = idx >> 4, k8 = idx & 15;                                     \
            int grow = g_gqidx[rs_ + m];                                         \
            CP_ASYNC16(smem_u32(&Ash[m * MS_SAH + k8 * 8]),                      \
                       g_colh + (size_t)grow * D + k8 * 8);                      \
        }                                                                        \
    }                                                                            \
} while (0)

template <int NT>
__device__ __forceinline__ void ms_body(__half* Ash, const __half* Bsh, float* red,
                                        const float* s_cv, float* s_cm,
                                        float* __restrict__ out,
                                        int t, int c, int tstart, int tend, int nc) {
    int w = t >> 5, lane = t & 31, g = lane >> 2, tg = lane & 3;
    int mw = w & 1, nw = w >> 1;
    int m_warp = mw * 64;

    CP_WAIT0();
    __syncthreads();
    {
        float p = -INFINITY;
        if (t < nc) {
            const __half* row = Bsh + t * MS_SBH;
            float s = 0.f;
#pragma unroll 16
            for (int k = 0; k < 128; k += 2) {
                __half2 h2 = *(const __half2*)(row + k);
                float2 f2 = __half22float2(h2);
                s += s_cv[k] * f2.x + s_cv[k + 1] * f2.y;
            }
            p = s;
        }
#pragma unroll
        for (int o = 16; o; o >>= 1) p = fmaxf(p, __shfl_xor_sync(0xffffffffu, p, o));
        if (lane == 0) s_cm[1 + w] = p;
    }
    __syncthreads();
    if (t == 0) {
        float b = s_cm[1];
        for (int i = 2; i <= 8; i++) b = fmaxf(b, s_cm[i]);
        s_cm[0] = b;
    }
    __syncthreads();
    float cmax = s_cm[0];

    for (int tt = tstart; tt < tend; tt++) {
        CP_WAIT0();
        __syncthreads();

        float acc[4][2 * NT][4];
#pragma unroll
        for (int mt = 0; mt < 4; mt++)
#pragma unroll
            for (int j = 0; j < 2 * NT; j++)
#pragma unroll
                for (int k = 0; k < 4; k++) acc[mt][j][k] = 0.f;

#pragma unroll
        for (int ks = 0; ks < 8; ks++) {
            int k0 = ks * 16;
            uint32_t afr[4][4], bfr[2 * NT][2];
#pragma unroll
            for (int mt = 0; mt < 4; mt++) {
                int base = m_warp + mt * 16;
                afr[mt][0] = *(const uint32_t*)&Ash[(base + g)     * MS_SAH + k0 + 2 * tg];
                afr[mt][1] = *(const uint32_t*)&Ash[(base + g + 8) * MS_SAH + k0 + 2 * tg];
                afr[mt][2] = *(const uint32_t*)&Ash[(base + g)     * MS_SAH + k0 + 2 * tg + 8];
                afr[mt][3] = *(const uint32_t*)&Ash[(base + g + 8) * MS_SAH + k0 + 2 * tg + 8];
            }
#pragma unroll
            for (int nt = 0; nt < NT; nt++)
#pragma unroll
                for (int s2 = 0; s2 < 2; s2++) {
                    int n = nt * 64 + nw * 16 + s2 * 8 + g;
                    bfr[nt * 2 + s2][0] = *(const uint32_t*)&Bsh[n * MS_SBH + k0 + 2 * tg];
                    bfr[nt * 2 + s2][1] = *(const uint32_t*)&Bsh[n * MS_SBH + k0 + 2 * tg + 8];
                }
#pragma unroll
            for (int mt = 0; mt < 4; mt++)
#pragma unroll
                for (int j = 0; j < 2 * NT; j++)
                    mma_f16(acc[mt][j], afr[mt], bfr[j]);
        }

        float rp[4][2];
#pragma unroll
        for (int mt = 0; mt < 4; mt++) { rp[mt][0] = -INFINITY; rp[mt][1] = -INFINITY; }
#pragma unroll
        for (int nt = 0; nt < NT; nt++)
#pragma unroll
            for (int s2 = 0; s2 < 2; s2++)
#pragma unroll
                for (int mt = 0; mt < 4; mt++)
#pragma unroll
                    for (int k = 0; k < 4; k++) {
                        int j = nt * 64 + nw * 16 + s2 * 8 + 2 * tg + (k & 1);
                        if (j < nc)
                            rp[mt][k >> 1] = fmaxf(rp[mt][k >> 1], acc[mt][nt * 2 + s2][k]);
                    }
#pragma unroll
        for (int off = 1; off <= 2; off <<= 1)
#pragma unroll
            for (int mt = 0; mt < 4; mt++)
#pragma unroll
                for (int h = 0; h < 2; h++)
                    rp[mt][h] = fmaxf(rp[mt][h], __shfl_xor_sync(0xffffffffu, rp[mt][h], off));
        if (tg == 0) {
#pragma unroll
            for (int mt = 0; mt < 4; mt++)
#pragma unroll
                for (int h = 0; h < 2; h++)
                    red[nw * 128 + m_warp + mt * 16 + g + 8 * h] = rp[mt][h];
        }
        __syncthreads();

        if (tt + 1 < tend) {
            MS_STAGEA(tt + 1);
            CP_COMMIT();
        }

        if (t < 64) {
            int qs = g_tile_qs[tt], qe = g_tile_qe[tt];
            int qi = qs + t;
            if (qi < qe) {
                int rs = g_tile_rs[tt];
                int r0 = g_qoff[qi] - rs;
                int r1 = g_qoff[qi + 1] - rs;
                float s = 0.f;
                for (int r = r0; r < r1; r++) {
                    float mx = fmaxf(fmaxf(red[r], red[128 + r]),
                                     fmaxf(red[256 + r], red[384 + r]));
                    s += mx;
                }
                float nu = g_denom[qi];
                out[qi * CC + c] = ((31.f - nu) * cmax + s) / nu;
            }
        }
    }
}

__global__ __launch_bounds__(256, 2) void maxsim_kernel(const float* __restrict__ bias,
                                                        float* __restrict__ out) {
    if (blockIdx.x == 0 && blockIdx.y == 0 && threadIdx.x == 0) g_nun = 0;

    extern __shared__ char smc[];
    __half* Ash   = (__half*)smc;
    __half* Bsh   = Ash + MSA_HALFS;
    float* red    = (float*)(Bsh + MSB_HALFS);
    int*   sidx   = (int*)(red + 4 * 128);
    float* s_cv   = (float*)(sidx + 256);
    float* s_cm   = s_cv + 128;

    int t  = threadIdx.x;
    int c  = blockIdx.x;
    int yy = blockIdx.y;

    int ntiles = g_ntiles;
    int ht = (ntiles + 1) >> 1;
    int tstart = yy ? ht : 0;
    int tend   = yy ? ntiles : ht;
    if (tstart >= tend) return;

    int nc = g_cnt[c];
    int NT = (nc + 63) >> 6;

    sidx[t] = g_idx[c * 256 + t];
    {
        __shared__ float s_cr[4];
        float v = (t < D) ? bias[t] : 0.f;
        float sq = v * v;
#pragma unroll
        for (int o = 16; o; o >>= 1) sq += __shfl_xor_sync(0xffffffffu, sq, o);
        if ((t & 31) == 0 && t < D) s_cr[t >> 5] = sq;
        __syncthreads();
        if (t < D) {
            float tot = s_cr[0] + s_cr[1] + s_cr[2] + s_cr[3];
            s_cv[t] = v / fmaxf(sqrtf(tot), 1e-12f);
        }
    }
    __syncthreads();

    {
        const __half* base = g_colh + (size_t)(QROWS + c * CT) * D;
        int chunks = nc * 16;
#pragma unroll
        for (int j = 0; j < 16; j++) {
            int idx = t + j * 256;
            if (idx < chunks) {
                int n = idx >> 4, k8 = idx & 15;
                CP_ASYNC16(smem_u32(&Bsh[n * MS_SBH + k8 * 8]),
                           base + (size_t)sidx[n] * D + k8 * 8);
            }
        }
    }
    CP_COMMIT();

    MS_STAGEA(tstart);
    CP_COMMIT();

    if (NT == 2)      ms_body<2>(Ash, Bsh, red, s_cv, s_cm, out, t, c, tstart, tend, nc);
    else if (NT == 3) ms_body<3>(Ash, Bsh, red, s_cv, s_cm, out, t, c, tstart, tend, nc);
    else if (NT == 1) ms_body<1>(Ash, Bsh, red, s_cv, s_cm, out, t, c, tstart, tend, nc);
    else              ms_body<4>(Ash, Bsh, red, s_cv, s_cm, out, t, c, tstart, tend, nc);
}

// ---------------------------------------------------------------------------
extern "C" void kernel_launch(void* const* d_in, const int* in_sizes, int n_in,
                              void* d_out, int out_size) {
    const float* qh  = (const float*)d_in[0];
    const float* ch  = (const float*)d_in[1];
    const float* Wm  = (const float*)d_in[2];
    const float* bia = (const float*)d_in[3];
    const int*   qm  = (const int*)d_in[4];
    const int*   cm  = (const int*)d_in[5];
    float* out = (float*)d_out;

    cudaFuncSetAttribute(proj_kernel,
                         cudaFuncAttributeMaxDynamicSharedMemorySize,
                         P_SMEM_BYTES);
    cudaFuncSetAttribute(maxsim_kernel,
                         cudaFuncAttributeMaxDynamicSharedMemorySize,
                         MS_SMEM_BYTES);

    unlist_kernel<<<263, 256>>>(qm, cm);
    proj_kernel<<<PROJ_BLKS + AUX_BLKS, 256, P_SMEM_BYTES>>>(qh, ch, Wm, bia, qm, cm, out);
    maxsim_kernel<<<dim3(CC, 2), 256, MS_SMEM_BYTES>>>(bia, out);
}

// round 16
// speedup vs baseline: 1.2650x; 1.2650x over previous
#include <cuda_runtime.h>
#include <cuda_fp16.h>
#include <math.h>
#include <stdint.h>

// Problem dims
#define Q    64
#define SQ   32
#define CC   256
#define SC   256
#define H    768
#define D    128
#define QT   31
#define CT   255
#define QROWS (Q*QT)     // 1984
#define CROWS (CC*CT)    // 65280
#define NROWS (QROWS+CROWS)

// Scratch
__device__ __half g_colh[(size_t)NROWS * D];
__device__ float  g_denom[Q];
__device__ int    g_idx[CC * 256];
__device__ int    g_cnt[CC];
__device__ int    g_qoff[Q + 1];
__device__ int    g_gqidx[QROWS];
__device__ int    g_tile_qs[16], g_tile_qe[16], g_tile_rs[16];
__device__ int    g_ntiles;
__device__ int    g_nun;            // ticket counter; reset by maxsim at sequence end
__device__ int    g_unrows[NROWS];

// ---------------------------------------------------------------------------
// helpers
// ---------------------------------------------------------------------------
__device__ __forceinline__ void mma_tf32(float* c, const uint32_t* a, const uint32_t* b) {
    asm volatile(
        "mma.sync.aligned.m16n8k8.row.col.f32.tf32.tf32.f32 "
        "{%0,%1,%2,%3},{%4,%5,%6,%7},{%8,%9},{%0,%1,%2,%3};\n"
        : "+f"(c[0]), "+f"(c[1]), "+f"(c[2]), "+f"(c[3])
        : "r"(a[0]), "r"(a[1]), "r"(a[2]), "r"(a[3]), "r"(b[0]), "r"(b[1]));
}
__device__ __forceinline__ void mma_f16(float* c, const uint32_t* a, const uint32_t* b) {
    asm volatile(
        "mma.sync.aligned.m16n8k16.row.col.f32.f16.f16.f32 "
        "{%0,%1,%2,%3},{%4,%5,%6,%7},{%8,%9},{%0,%1,%2,%3};\n"
        : "+f"(c[0]), "+f"(c[1]), "+f"(c[2]), "+f"(c[3])
        : "r"(a[0]), "r"(a[1]), "r"(a[2]), "r"(a[3]), "r"(b[0]), "r"(b[1]));
}
__device__ __forceinline__ uint32_t smem_u32(const void* p) {
    uint32_t a;
    asm("{ .reg .u64 t; cvta.to.shared.u64 t, %1; cvt.u32.u64 %0, t; }" : "=r"(a) : "l"(p));
    return a;
}
#define CP_ASYNC16(dst_u32, src_ptr) \
    asm volatile("cp.async.ca.shared.global [%0], [%1], 16;" :: "r"(dst_u32), "l"(src_ptr))
#define CP_COMMIT() asm volatile("cp.async.commit_group;" ::: "memory")
#define CP_WAIT2()  asm volatile("cp.async.wait_group 2;" ::: "memory")
#define CP_WAIT1()  asm volatile("cp.async.wait_group 1;" ::: "memory")
#define CP_WAIT0()  asm volatile("cp.async.wait_group 0;" ::: "memory")

// ---------------------------------------------------------------------------
// Kernel 1: setup — ONE ROLE PER BLOCK (round-14 proven).
// Grid 840: [0,320) pooled | [320,583) unlist | [583,839) compact | 839 prep.
// ---------------------------------------------------------------------------
__global__ void setup_kernel(const float* __restrict__ qh,
                             const float* __restrict__ ch,
                             const float* __restrict__ bias,
                             const int*   __restrict__ qm,
                             const int*   __restrict__ cm,
                             float* __restrict__ out) {
    int b = blockIdx.x, t = threadIdx.x;
    int lane = t & 31, w = t >> 5;

    if (b < 320) {
        // ---- pooled (fp32 exact) ----
        __shared__ float red[8];
        const float* src;
        float mask;
        float* dst;
        if (b < Q) {
            src  = qh + (size_t)b * SQ * H;
            mask = (float)qm[b * SQ];
            dst  = out + Q * CC + (size_t)b * H;
        } else {
            int c = b - Q;
            src  = ch + (size_t)c * SC * H;
            mask = (float)cm[c * SC];
            dst  = out + Q * CC + Q * H + (size_t)c * H;
        }
        float v[3];
        float s = 0.f;
#pragma unroll
        for (int it = 0; it < 3; it++) {
            float x = src[t + it * 256] * mask;
            v[it] = x;
            s += x * x;
        }
#pragma unroll
        for (int o = 16; o; o >>= 1) s += __shfl_xor_sync(0xffffffffu, s, o);
        if (lane == 0) red[w] = s;
        __syncthreads();
        if (t < 8) {
            float ss = red[t];
#pragma unroll
            for (int o = 4; o; o >>= 1) ss += __shfl_xor_sync(0xffu, ss, o);
            if (t == 0) red[0] = ss;
        }
        __syncthreads();
        float inv = 1.f / fmaxf(sqrtf(red[0]), 1e-12f);
#pragma unroll
        for (int it = 0; it < 3; it++) dst[t + it * 256] = v[it] * inv;

    } else if (b < 583) {
        // ---- unlist (ticketed compaction of unmasked rows) ----
        int r = (b - 320) * 256 + t;
        int m = 0;
        if (r < NROWS) {
            if (r < QROWS) { int q = r / QT, i = r % QT; m = qm[q * SQ + i + 1]; }
            else { int rc = r - QROWS; int c = rc / CT, j = rc % CT; m = cm[c * SC + j + 1]; }
        }
        unsigned bal = __ballot_sync(0xffffffffu, m != 0);
        int cnt = __popc(bal);
        int pre = __popc(bal & ((1u << lane) - 1));
        int base = 0;
        if (lane == 0 && cnt) base = atomicAdd(&g_nun, cnt);
        base = __shfl_sync(0xffffffffu, base, 0);
        if (m) g_unrows[base + pre] = r;

    } else if (b < 839) {
        // ---- doc compaction + cvec rep-row write ----
        __shared__ int wcnt[8];
        __shared__ int firstmask;
        __shared__ float s_cr[4];
        int c = b - 583;
        if (t == 0) firstmask = 1 << 30;
        __syncthreads();
        int valid = (t >= 1);
        int m = valid ? cm[c * SC + t] : 0;
        unsigned bal = __ballot_sync(0xffffffffu, m != 0);
        int pre = __popc(bal & ((1u << lane) - 1));
        if (lane == 0) wcnt[w] = __popc(bal);
        if (valid && !m) atomicMin(&firstmask, t);
        __syncthreads();
        int off = 0;
        for (int i = 0; i < w; i++) off += wcnt[i];
        if (valid && m) g_idx[c * 256 + off + pre] = t - 1;
        if (t == 0) {
            int total = 0;
            for (int i = 0; i < 8; i++) total += wcnt[i];
            if (firstmask < 256) { g_idx[c * 256 + total] = firstmask - 1; total++; }
            g_cnt[c] = total;
        }
        float v = (t < D) ? bias[t] : 0.f;
        float sq = v * v;
#pragma unroll
        for (int o = 16; o; o >>= 1) sq += __shfl_xor_sync(0xffffffffu, sq, o);
        if (lane == 0 && t < D) s_cr[w] = sq;
        __syncthreads();
        if (firstmask < 256 && t < D) {
            float tot = s_cr[0] + s_cr[1] + s_cr[2] + s_cr[3];
            float inv = 1.f / fmaxf(sqrtf(tot), 1e-12f);
            size_t row = (size_t)QROWS + (size_t)c * CT + (firstmask - 1);
            g_colh[row * D + t] = __float2half_rn(v * inv);
        }

    } else {
        // ---- q-side prep ----
        __shared__ int s_nu[64];
        __shared__ int s_qoff[65];
        if (t < 64) {
            int nu = 0;
            for (int i = 1; i < SQ; i++) nu += (qm[t * SQ + i] != 0);
            s_nu[t] = nu;
            g_denom[t] = (float)nu;
        }
        __syncthreads();
        if (t == 0) {
            int acc = 0;
            for (int q = 0; q < 64; q++) { s_qoff[q] = acc; acc += s_nu[q]; }
            s_qoff[64] = acc;
            int ntiles = 0, cur = 0;
            while (cur < 64) {
                int qs = cur;
                while (cur < 64 && (s_qoff[cur + 1] - s_qoff[qs]) <= 128) cur++;
                g_tile_qs[ntiles] = qs;
                g_tile_qe[ntiles] = cur;
                g_tile_rs[ntiles] = s_qoff[qs];
                ntiles++;
            }
            g_ntiles = ntiles;
        }
        __syncthreads();
        if (t < 65) g_qoff[t] = s_qoff[t];
        if (t < 64) {
            int pos = s_qoff[t];
            for (int i = 1; i < SQ; i++)
                if (qm[t * SQ + i] != 0) g_gqidx[pos++] = t * QT + i - 1;
        }
    }
}

// ---------------------------------------------------------------------------
// Kernel 2: projection + l2norm over unmasked rows.
// ROUND-16 CHANGE: 3-stage cp.async pipeline (prefetch distance 2).
// smem 3x(A+W) + extras = ~109.6 KB -> still 2 CTA/SM.
// ---------------------------------------------------------------------------
#define P_SA 36
#define P_SW 132
#define P_AS_F (128 * P_SA)
#define P_WS_F (32 * P_SW)
#define P_STG_F (P_AS_F + P_WS_F)
#define P_SMEM_FLOATS (3*P_STG_F + 256 + 128 + 256 + 128 + 128)
#define P_SMEM_BYTES (P_SMEM_FLOATS * 4)

__global__ __launch_bounds__(256) void proj_kernel(const float* __restrict__ qh,
                                                   const float* __restrict__ ch,
                                                   const float* __restrict__ Wm,
                                                   const float* __restrict__ bias) {
    int nun = g_nun;
    if (blockIdx.x * 128 >= nun) return;

    extern __shared__ float psm[];
    // Stage s: A at psm + s*P_STG_F, W at psm + s*P_STG_F + P_AS_F
    const float** srcp = (const float**)(psm + 3 * P_STG_F);
    int*   rowid  = (int*)(srcp + 128);
    float* rowsq  = (float*)(rowid + 128);
    float* invn   = rowsq + 256;
    float* s_bias = invn + 128;

    int t = threadIdx.x;
    int w = t >> 5, lane = t & 31, g = lane >> 2, tg = lane & 3;
    int mw = w & 3, nw = w >> 2;
    int m_warp = mw * 32, n_warp = nw * 64;

    if (t < 128) {
        s_bias[t] = bias[t];
        int idx = blockIdx.x * 128 + t;
        if (idx < nun) {
            int r = g_unrows[idx];
            rowid[t] = r;
            if (r < QROWS) {
                int q = r / QT, i = r % QT;
                srcp[t] = qh + (size_t)(q * SQ + i + 1) * H;
            } else {
                int rc = r - QROWS;
                int c = rc / CT, j = rc % CT;
                srcp[t] = ch + (size_t)(c * SC + j + 1) * H;
            }
        } else {
            rowid[t] = -1;
            srcp[t] = qh;
        }
    }
    __syncthreads();

#define PSTAGE(SBUF, KT) do {                                                   \
    float* bufA_ = psm + (SBUF) * P_STG_F;                                      \
    float* bufW_ = bufA_ + P_AS_F;                                              \
    _Pragma("unroll")                                                           \
    for (int itc = 0; itc < 4; itc++) {                                         \
        int idx = t + itc * 256;                                                \
        int m = idx >> 3, k4 = idx & 7;                                         \
        CP_ASYNC16(smem_u32(bufA_ + m * P_SA + k4 * 4), srcp[m] + (KT) + k4 * 4); \
    }                                                                           \
    _Pragma("unroll")                                                           \
    for (int itc = 0; itc < 4; itc++) {                                         \
        int idx = t + itc * 256;                                                \
        int k = idx >> 5, d4 = idx & 31;                                        \
        CP_ASYNC16(smem_u32(bufW_ + k * P_SW + d4 * 4),                         \
                   Wm + (size_t)((KT) + k) * D + d4 * 4);                       \
    }                                                                           \
} while (0)

    PSTAGE(0, 0);
    CP_COMMIT();
    PSTAGE(1, 32);
    CP_COMMIT();

    float acc[2][8][4];
#pragma unroll
    for (int mt = 0; mt < 2; mt++)
#pragma unroll
        for (int nt4 = 0; nt4 < 8; nt4++)
#pragma unroll
            for (int i = 0; i < 4; i++) acc[mt][nt4][i] = 0.f;

    int sb = 0;      // stage buffer holding tile `it`
    for (int it = 0; it < 24; it++) {
        if (it < 22) {
            int nb = sb + 2; if (nb >= 3) nb -= 3;
            PSTAGE(nb, (it + 2) * 32);
            CP_COMMIT();
            CP_WAIT2();                 // >=2 outstanding allowed; tile `it` done
        } else if (it == 22) {
            CP_WAIT1();
        } else {
            CP_WAIT0();
        }
        __syncthreads();
        const float* A = psm + sb * P_STG_F;
        const float* W = A + P_AS_F;
#pragma unroll
        for (int ks = 0; ks < 4; ks++) {
            int k0 = ks * 8;
            uint32_t afr[2][4], bfr[8][2];
#pragma unroll
            for (int mt = 0; mt < 2; mt++) {
                int base = m_warp + mt * 16;
                afr[mt][0] = __float_as_uint(A[(base + g)     * P_SA + k0 + tg]);
                afr[mt][1] = __float_as_uint(A[(base + g + 8) * P_SA + k0 + tg]);
                afr[mt][2] = __float_as_uint(A[(base + g)     * P_SA + k0 + tg + 4]);
                afr[mt][3] = __float_as_uint(A[(base + g + 8) * P_SA + k0 + tg + 4]);
            }
#pragma unroll
            for (int nt4 = 0; nt4 < 8; nt4++) {
                int col = n_warp + nt4 * 8 + g;
                bfr[nt4][0] = __float_as_uint(W[(k0 + tg)     * P_SW + col]);
                bfr[nt4][1] = __float_as_uint(W[(k0 + tg + 4) * P_SW + col]);
            }
#pragma unroll
            for (int mt = 0; mt < 2; mt++)
#pragma unroll
                for (int nt4 = 0; nt4 < 8; nt4++)
                    mma_tf32(acc[mt][nt4], afr[mt], bfr[nt4]);
        }
        __syncthreads();
        sb++; if (sb == 3) sb = 0;
    }

#pragma unroll
    for (int mt = 0; mt < 2; mt++)
#pragma unroll
        for (int nt4 = 0; nt4 < 8; nt4++)
#pragma unroll
            for (int i = 0; i < 4; i++)
                acc[mt][nt4][i] += s_bias[n_warp + nt4 * 8 + 2 * tg + (i & 1)];

    float pr[2][2];
#pragma unroll
    for (int mt = 0; mt < 2; mt++)
#pragma unroll
        for (int h = 0; h < 2; h++) {
            float s = 0.f;
#pragma unroll
            for (int nt4 = 0; nt4 < 8; nt4++) {
                float c0 = acc[mt][nt4][2 * h], c1 = acc[mt][nt4][2 * h + 1];
                s += c0 * c0 + c1 * c1;
            }
            pr[mt][h] = s;
        }
#pragma unroll
    for (int off = 1; off <= 2; off <<= 1) {
#pragma unroll
        for (int mt = 0; mt < 2; mt++)
#pragma unroll
            for (int h = 0; h < 2; h++)
                pr[mt][h] += __shfl_xor_sync(0xffffffffu, pr[mt][h], off);
    }
    if (tg == 0) {
#pragma unroll
        for (int mt = 0; mt < 2; mt++)
#pragma unroll
            for (int h = 0; h < 2; h++)
                rowsq[(m_warp + mt * 16 + g + 8 * h) * 2 + nw] = pr[mt][h];
    }
    __syncthreads();
    if (t < 128) {
        float s = rowsq[t * 2] + rowsq[t * 2 + 1];
        invn[t] = 1.f / fmaxf(sqrtf(s), 1e-12f);
    }
    __syncthreads();

#pragma unroll
    for (int mt = 0; mt < 2; mt++)
#pragma unroll
        for (int h = 0; h < 2; h++) {
            int r = m_warp + mt * 16 + g + 8 * h;
            int grow = rowid[r];
            if (grow >= 0) {
                float inv = invn[r];
                __half* dst = g_colh + (size_t)grow * D;
#pragma unroll
                for (int nt4 = 0; nt4 < 8; nt4++) {
                    int col = n_warp + nt4 * 8 + 2 * tg;
                    *(__half2*)(dst + col) =
                        __floats2half2_rn(acc[mt][nt4][2 * h] * inv,
                                          acc[mt][nt4][2 * h + 1] * inv);
                }
            }
        }
#undef PSTAGE
}

// ---------------------------------------------------------------------------
// Kernel 3: fused maxsim — unchanged (round-14 proven, 2 CTA/SM).
// ---------------------------------------------------------------------------
#define MS_SAH 136
#define MS_SBH 136
#define MSA_HALFS (128 * MS_SAH)
#define MSB_HALFS (256 * MS_SBH)
#define MS_SMEM_BYTES ((MSA_HALFS + MSB_HALFS) * 2 + (4 * 128) * 4 + 256 * 4 + 128 * 4 + 12 * 4)

#define MS_STAGEA(TT_) do {                                                      \
    int rs_ = g_tile_rs[TT_];                                                    \
    int rows_ = g_qoff[g_tile_qe[TT_]] - rs_;                                    \
    int chunks_ = rows_ * 16;                                                    \
    _Pragma("unroll")                                                            \
    for (int j = 0; j < 8; j++) {                                                \
        int idx = t + j * 256;                                                   \
        if (idx < chunks_) {                                                     \
            int m = idx >> 4, k8 = idx & 15;                                     \
            int grow = g_gqidx[rs_ + m];                                         \
            CP_ASYNC16(smem_u32(&Ash[m * MS_SAH + k8 * 8]),                      \
                       g_colh + (size_t)grow * D + k8 * 8);                      \
        }                                                                        \
    }                                                                            \
} while (0)

template <int NT>
__device__ __forceinline__ void ms_body(__half* Ash, const __half* Bsh, float* red,
                                        const float* s_cv, float* s_cm,
                                        float* __restrict__ out,
                                        int t, int c, int tstart, int tend, int nc) {
    int w = t >> 5, lane = t & 31, g = lane >> 2, tg = lane & 3;
    int mw = w & 1, nw = w >> 1;
    int m_warp = mw * 64;

    CP_WAIT0();
    __syncthreads();
    {
        float p = -INFINITY;
        if (t < nc) {
            const __half* row = Bsh + t * MS_SBH;
            float s = 0.f;
#pragma unroll 16
            for (int k = 0; k < 128; k += 2) {
                __half2 h2 = *(const __half2*)(row + k);
                float2 f2 = __half22float2(h2);
                s += s_cv[k] * f2.x + s_cv[k + 1] * f2.y;
            }
            p = s;
        }
#pragma unroll
        for (int o = 16; o; o >>= 1) p = fmaxf(p, __shfl_xor_sync(0xffffffffu, p, o));
        if (lane == 0) s_cm[1 + w] = p;
    }
    __syncthreads();
    if (t == 0) {
        float b = s_cm[1];
        for (int i = 2; i <= 8; i++) b = fmaxf(b, s_cm[i]);
        s_cm[0] = b;
    }
    __syncthreads();
    float cmax = s_cm[0];

    for (int tt = tstart; tt < tend; tt++) {
        CP_WAIT0();
        __syncthreads();

        float acc[4][2 * NT][4];
#pragma unroll
        for (int mt = 0; mt < 4; mt++)
#pragma unroll
            for (int j = 0; j < 2 * NT; j++)
#pragma unroll
                for (int k = 0; k < 4; k++) acc[mt][j][k] = 0.f;

#pragma unroll
        for (int ks = 0; ks < 8; ks++) {
            int k0 = ks * 16;
            uint32_t afr[4][4], bfr[2 * NT][2];
#pragma unroll
            for (int mt = 0; mt < 4; mt++) {
                int base = m_warp + mt * 16;
                afr[mt][0] = *(const uint32_t*)&Ash[(base + g)     * MS_SAH + k0 + 2 * tg];
                afr[mt][1] = *(const uint32_t*)&Ash[(base + g + 8) * MS_SAH + k0 + 2 * tg];
                afr[mt][2] = *(const uint32_t*)&Ash[(base + g)     * MS_SAH + k0 + 2 * tg + 8];
                afr[mt][3] = *(const uint32_t*)&Ash[(base + g + 8) * MS_SAH + k0 + 2 * tg + 8];
            }
#pragma unroll
            for (int nt = 0; nt < NT; nt++)
#pragma unroll
                for (int s2 = 0; s2 < 2; s2++) {
                    int n = nt * 64 + nw * 16 + s2 * 8 + g;
                    bfr[nt * 2 + s2][0] = *(const uint32_t*)&Bsh[n * MS_SBH + k0 + 2 * tg];
                    bfr[nt * 2 + s2][1] = *(const uint32_t*)&Bsh[n * MS_SBH + k0 + 2 * tg + 8];
                }
#pragma unroll
            for (int mt = 0; mt < 4; mt++)
#pragma unroll
                for (int j = 0; j < 2 * NT; j++)
                    mma_f16(acc[mt][j], afr[mt], bfr[j]);
        }

        float rp[4][2];
#pragma unroll
        for (int mt = 0; mt < 4; mt++) { rp[mt][0] = -INFINITY; rp[mt][1] = -INFINITY; }
#pragma unroll
        for (int nt = 0; nt < NT; nt++)
#pragma unroll
            for (int s2 = 0; s2 < 2; s2++)
#pragma unroll
                for (int mt = 0; mt < 4; mt++)
#pragma unroll
                    for (int k = 0; k < 4; k++) {
                        int j = nt * 64 + nw * 16 + s2 * 8 + 2 * tg + (k & 1);
                        if (j < nc)
                            rp[mt][k >> 1] = fmaxf(rp[mt][k >> 1], acc[mt][nt * 2 + s2][k]);
                    }
#pragma unroll
        for (int off = 1; off <= 2; off <<= 1)
#pragma unroll
            for (int mt = 0; mt < 4; mt++)
#pragma unroll
                for (int h = 0; h < 2; h++)
                    rp[mt][h] = fmaxf(rp[mt][h], __shfl_xor_sync(0xffffffffu, rp[mt][h], off));
        if (tg == 0) {
#pragma unroll
            for (int mt = 0; mt < 4; mt++)
#pragma unroll
                for (int h = 0; h < 2; h++)
                    red[nw * 128 + m_warp + mt * 16 + g + 8 * h] = rp[mt][h];
        }
        __syncthreads();

        if (tt + 1 < tend) {
            MS_STAGEA(tt + 1);
            CP_COMMIT();
        }

        if (t < 64) {
            int qs = g_tile_qs[tt], qe = g_tile_qe[tt];
            int qi = qs + t;
            if (qi < qe) {
                int rs = g_tile_rs[tt];
                int r0 = g_qoff[qi] - rs;
                int r1 = g_qoff[qi + 1] - rs;
                float s = 0.f;
                for (int r = r0; r < r1; r++) {
                    float mx = fmaxf(fmaxf(red[r], red[128 + r]),
                                     fmaxf(red[256 + r], red[384 + r]));
                    s += mx;
                }
                float nu = g_denom[qi];
                out[qi * CC + c] = ((31.f - nu) * cmax + s) / nu;
            }
        }
    }
}

__global__ __launch_bounds__(256, 2) void maxsim_kernel(const float* __restrict__ bias,
                                                        float* __restrict__ out) {
    if (blockIdx.x == 0 && blockIdx.y == 0 && threadIdx.x == 0) g_nun = 0;

    extern __shared__ char smc[];
    __half* Ash   = (__half*)smc;
    __half* Bsh   = Ash + MSA_HALFS;
    float* red    = (float*)(Bsh + MSB_HALFS);
    int*   sidx   = (int*)(red + 4 * 128);
    float* s_cv   = (float*)(sidx + 256);
    float* s_cm   = s_cv + 128;

    int t  = threadIdx.x;
    int c  = blockIdx.x;
    int yy = blockIdx.y;

    int ntiles = g_ntiles;
    int ht = (ntiles + 1) >> 1;
    int tstart = yy ? ht : 0;
    int tend   = yy ? ntiles : ht;
    if (tstart >= tend) return;

    int nc = g_cnt[c];
    int NT = (nc + 63) >> 6;

    sidx[t] = g_idx[c * 256 + t];
    {
        __shared__ float s_cr[4];
        float v = (t < D) ? bias[t] : 0.f;
        float sq = v * v;
#pragma unroll
        for (int o = 16; o; o >>= 1) sq += __shfl_xor_sync(0xffffffffu, sq, o);
        if ((t & 31) == 0 && t < D) s_cr[t >> 5] = sq;
        __syncthreads();
        if (t < D) {
            float tot = s_cr[0] + s_cr[1] + s_cr[2] + s_cr[3];
            s_cv[t] = v / fmaxf(sqrtf(tot), 1e-12f);
        }
    }
    __syncthreads();

    {
        const __half* base = g_colh + (size_t)(QROWS + c * CT) * D;
        int chunks = nc * 16;
#pragma unroll
        for (int j = 0; j < 16; j++) {
            int idx = t + j * 256;
            if (idx < chunks) {
                int n = idx >> 4, k8 = idx & 15;
                CP_ASYNC16(smem_u32(&Bsh[n * MS_SBH + k8 * 8]),
                           base + (size_t)sidx[n] * D + k8 * 8);
            }
        }
    }
    CP_COMMIT();

    MS_STAGEA(tstart);
    CP_COMMIT();

    if (NT == 2)      ms_body<2>(Ash, Bsh, red, s_cv, s_cm, out, t, c, tstart, tend, nc);
    else if (NT == 3) ms_body<3>(Ash, Bsh, red, s_cv, s_cm, out, t, c, tstart, tend, nc);
    else if (NT == 1) ms_body<1>(Ash, Bsh, red, s_cv, s_cm, out, t, c, tstart, tend, nc);
    else              ms_body<4>(Ash, Bsh, red, s_cv, s_cm, out, t, c, tstart, tend, nc);
}

// ---------------------------------------------------------------------------
extern "C" void kernel_launch(void* const* d_in, const int* in_sizes, int n_in,
                              void* d_out, int out_size) {
    const float* qh  = (const float*)d_in[0];
    const float* ch  = (const float*)d_in[1];
    const float* Wm  = (const float*)d_in[2];
    const float* bia = (const float*)d_in[3];
    const int*   qm  = (const int*)d_in[4];
    const int*   cm  = (const int*)d_in[5];
    float* out = (float*)d_out;

    cudaFuncSetAttribute(proj_kernel,
                         cudaFuncAttributeMaxDynamicSharedMemorySize,
                         P_SMEM_BYTES);
    cudaFuncSetAttribute(maxsim_kernel,
                         cudaFuncAttributeMaxDynamicSharedMemorySize,
                         MS_SMEM_BYTES);

    setup_kernel<<<840, 256>>>(qh, ch, bia, qm, cm, out);
    proj_kernel<<<(NROWS + 127) / 128, 256, P_SMEM_BYTES>>>(qh, ch, Wm, bia);
    maxsim_kernel<<<dim3(CC, 2), 256, MS_SMEM_BYTES>>>(bia, out);
}